// round 9
// baseline (speedup 1.0000x reference)
#include <cuda_runtime.h>
#include <cuda_bf16.h>
#include <cstdint>

#define SLEN 1024
#define BATCH 256
#define DIN 64
#define HID 128
#define KW 100            // uint2 (hi,lo word pair) per batch row: 96 real + 4 pad

// h outputs for fc pass: [dir][b][t][j]
__device__ float g_h[2u * BATCH * SLEN * HID];

typedef unsigned int u32;
typedef unsigned long long u64;

static __device__ __forceinline__ u32 smem_u32(const void* p) {
    u32 a; asm("{ .reg .u64 t; cvta.to.shared.u64 t, %1; cvt.u32.u64 %0, t; }" : "=r"(a) : "l"(p));
    return a;
}
static __device__ __forceinline__ u32 bfpack(float a0, float a1) {
    u32 r; asm("cvt.rn.bf16x2.f32 %0, %1, %2;" : "=r"(r) : "f"(a1), "f"(a0)); return r;
}
static __device__ __forceinline__ float bfres(float a) {
    return a - __bfloat162float(__float2bfloat16(a));
}
static __device__ __forceinline__ void mma16816(float c[4], const u32 a[4], const u32 b[2]) {
    asm("mma.sync.aligned.m16n8k16.row.col.f32.bf16.bf16.f32 "
        "{%0,%1,%2,%3}, {%4,%5,%6,%7}, {%8,%9}, {%0,%1,%2,%3};"
        : "+f"(c[0]), "+f"(c[1]), "+f"(c[2]), "+f"(c[3])
        : "r"(a[0]), "r"(a[1]), "r"(a[2]), "r"(a[3]), "r"(b[0]), "r"(b[1]));
}
static __device__ __forceinline__ float fast_tanh(float x) {
    float e, r;
    asm("ex2.approx.f32 %0, %1;" : "=f"(e) : "f"(x * 2.8853900817779268f));
    asm("rcp.approx.f32 %0, %1;" : "=f"(r) : "f"(e + 1.0f));
    return fmaf(-2.0f, r, 1.0f);
}

// ===== Recurrence: 128 CTAs in 64 clusters of 2.  Cluster = (dir, batch-group of 8).
// CTA rank r computes j in [64r, 64r+64).  Warps 0-3: K-chunks 0-5 (h[0:96]);
// warps 4-7: K-chunks 6-11 (h[96:128]|x).  Warp pair (p, p+4) -> m16 tile j0=64r+16p.
// h halves exchanged cross-CTA via st.shared::cluster + mbarrier.
__global__ __launch_bounds__(256, 1) __cluster_dims__(2, 1, 1)
void birnn_recur(const float* __restrict__ inputs,
                 const float* __restrict__ Whh_fw, const float* __restrict__ Whh_bw,
                 const float* __restrict__ Wih_fw, const float* __restrict__ Wih_bw,
                 const float* __restrict__ bih_fw, const float* __restrict__ bhh_fw,
                 const float* __restrict__ bih_bw, const float* __restrict__ bhh_bw)
{
    __shared__ uint2 C[2][8 * KW];          // B tile x2: [batch 8][k-pair(hi,lo) 96+4 pad]
    __shared__ __align__(16) float psum[4][32][4];
    __shared__ __align__(8) u64 mbar;

    const int tid  = threadIdx.x;
    const int lane = tid & 31;
    const int w    = tid >> 5;
    const int g  = lane >> 2;
    const int t4 = lane & 3;
    const int khalf = w >> 2;          // 0: kc 0-5, 1: kc 6-11
    const int p     = w & 3;           // tile pair id
    const u32 r   = blockIdx.x & 1;    // cluster rank
    const int cid = blockIdx.x >> 1;
    const int dir = cid >> 5;
    const int bb  = (cid & 31) * 8;
    const int j0  = 64 * (int)r + 16 * p;

    const float* Whh = dir ? Whh_bw : Whh_fw;
    const float* Wih = dir ? Wih_bw : Wih_fw;

    // ---- static A fragments: rows j0+g, j0+g+8, this warp's 6 K-chunks, hi+lo ----
    u32 ah[6][4], al[6][4];
    #pragma unroll
    for (int c = 0; c < 6; ++c) {
        const int kcg = khalf * 6 + c;
        const int kb  = 16 * kcg + 2 * t4;
        const float* r0 = (kcg < 8) ? (Whh + (j0 + g) * HID + kb)
                                    : (Wih + (j0 + g) * DIN + (kb - HID));
        const float* r1 = (kcg < 8) ? (Whh + (j0 + g + 8) * HID + kb)
                                    : (Wih + (j0 + g + 8) * DIN + (kb - HID));
        float2 v0 = *(const float2*)r0;
        float2 v1 = *(const float2*)r1;
        float2 v2 = *(const float2*)(r0 + 8);
        float2 v3 = *(const float2*)(r1 + 8);
        ah[c][0] = bfpack(v0.x, v0.y);  al[c][0] = bfpack(bfres(v0.x), bfres(v0.y));
        ah[c][1] = bfpack(v1.x, v1.y);  al[c][1] = bfpack(bfres(v1.x), bfres(v1.y));
        ah[c][2] = bfpack(v2.x, v2.y);  al[c][2] = bfpack(bfres(v2.x), bfres(v2.y));
        ah[c][3] = bfpack(v3.x, v3.y);  al[c][3] = bfpack(bfres(v3.x), bfres(v3.y));
    }

    float bias2[2];
    #pragma unroll
    for (int hh = 0; hh < 2; ++hh) {
        const int j = j0 + g + 8 * hh;
        bias2[hh] = dir ? (bih_bw[j] + bhh_bw[j]) : (bih_fw[j] + bhh_fw[j]);
    }

    // ---- init: zero B buffers, mbarrier ----
    for (int i = tid; i < 2 * 8 * KW; i += 256)
        ((uint2*)C)[i] = make_uint2(0u, 0u);
    if (tid == 0)
        asm volatile("mbarrier.init.shared.b64 [%0], 64;" :: "r"(smem_u32(&mbar)) : "memory");

    // ---- x loaders: warps 4-7 ----
    const int t0 = dir ? (SLEN - 1) : 0;
    const int dt = dir ? -1 : 1;
    const int xi = (w - 4) * 32 + lane;       // 0..127 for w>=4
    const int xb = (xi >> 4) & 7;
    const int xq = xi & 15;
    const float* xptr = inputs + ((size_t)(bb + xb) * SLEN + t0) * DIN + xq * 4;
    const int xe = xb * KW + 64 + xq * 2;     // uint2 entry index

    if (w >= 4) {
        float4 v = __ldg((const float4*)xptr);
        uint4 pk;
        pk.x = bfpack(v.x, v.y);  pk.y = bfpack(bfres(v.x), bfres(v.y));
        pk.z = bfpack(v.z, v.w);  pk.w = bfpack(bfres(v.z), bfres(v.w));
        *(uint4*)&C[0][xe] = pk;
    }
    __syncthreads();

    // ---- cluster handshake setup ----
    asm volatile("barrier.cluster.arrive.aligned;" ::: "memory");
    asm volatile("barrier.cluster.wait.aligned;" ::: "memory");

    const u32 mybar = smem_u32(&mbar);
    u32 peerbar, peerC;
    {
        const u32 myC = smem_u32(&C[0][0]);
        const u32 pr = r ^ 1u;
        asm("mapa.shared::cluster.u32 %0, %1, %2;" : "=r"(peerbar) : "r"(mybar), "r"(pr));
        asm("mapa.shared::cluster.u32 %0, %1, %2;" : "=r"(peerC)  : "r"(myC),  "r"(pr));
    }

    // ---- gmem h stream (warps 0-3, even g store) ----
    float* gb = g_h + ((size_t)(dir * BATCH + bb) * SLEN + t0) * HID;
    const long gstep = (long)dt * HID;

    for (int s = 0; s < SLEN; ++s) {
        const uint2* Rd = C[s & 1];

        // prefetch x(s+1)
        float4 xv = make_float4(0.f, 0.f, 0.f, 0.f);
        if (w >= 4 && s + 1 < SLEN)
            xv = __ldg((const float4*)(xptr + (long)dt * (s + 1) * DIN - (long)dt * s * DIN + ((long)dt * s * DIN)));  // placeholder; replaced below

        // (simple form: advance pointer)
        if (w >= 4 && s + 1 < SLEN)
            xv = __ldg((const float4*)(inputs + ((size_t)(bb + xb) * SLEN + (t0 + dt * (s + 1))) * DIN + xq * 4));

        // ---- B fragments (this warp's 6 kc) + 18 HMMA, 3 chains ----
        u32 bh[6][2], bl[6][2];
        #pragma unroll
        for (int c = 0; c < 6; ++c) {
            uint2 v0 = Rd[g * KW + (khalf * 6 + c) * 8 + t4];
            uint2 v1 = Rd[g * KW + (khalf * 6 + c) * 8 + t4 + 4];
            bh[c][0] = v0.x;  bl[c][0] = v0.y;
            bh[c][1] = v1.x;  bl[c][1] = v1.y;
        }
        float a0[4] = {0.f,0.f,0.f,0.f}, a1[4] = {0.f,0.f,0.f,0.f}, a2[4] = {0.f,0.f,0.f,0.f};
        #pragma unroll
        for (int c = 0; c < 6; ++c) {
            mma16816(a0, ah[c], bh[c]);
            mma16816(a1, ah[c], bl[c]);
            mma16816(a2, al[c], bh[c]);
        }
        float a[4];
        #pragma unroll
        for (int e = 0; e < 4; ++e) a[e] = a0[e] + a1[e] + a2[e];

        // ---- K-split partial exchange (warps 4-7 -> smem) ----
        if (w >= 4)
            *(float4*)psum[p][lane] = make_float4(a[0], a[1], a[2], a[3]);
        __syncthreads();

        if (w < 4) {
            // combine, activate
            float4 q = *(const float4*)psum[p][lane];
            float v[4];
            v[0] = fast_tanh(a[0] + q.x + bias2[0]);
            v[1] = fast_tanh(a[1] + q.y + bias2[0]);
            v[2] = fast_tanh(a[2] + q.z + bias2[1]);
            v[3] = fast_tanh(a[3] + q.w + bias2[1]);

            // pair j with j+1 via shfl (partner lane ^4 = g^1)
            float vp[4];
            #pragma unroll
            for (int e = 0; e < 4; ++e)
                vp[e] = __shfl_xor_sync(0xffffffffu, v[e], 4);

            if (!(g & 1)) {
                const int buf = (s + 1) & 1;
                #pragma unroll
                for (int e = 0; e < 4; ++e) {
                    const int b_ = 2 * t4 + (e & 1);
                    const int j_ = j0 + g + 8 * (e >> 1);       // even
                    const u32 hi = bfpack(v[e], vp[e]);
                    const u32 lo = bfpack(bfres(v[e]), bfres(vp[e]));
                    const int idx = b_ * KW + (j_ >> 1);
                    C[buf][idx] = make_uint2(hi, lo);            // local
                    u64 val; asm("mov.b64 %0, {%1, %2};" : "=l"(val) : "r"(hi), "r"(lo));
                    const u32 po = peerC + (u32)(buf * (8 * KW * 8) + idx * 8);
                    asm volatile("st.shared::cluster.b64 [%0], %1;" :: "r"(po), "l"(val) : "memory");
                    // gmem h stream (j, j+1)
                    *(float2*)(gb + (size_t)b_ * (SLEN * HID) + j_) = make_float2(v[e], vp[e]);
                }
                // signal peer: my 4 h entries written
                asm volatile("mbarrier.arrive.release.cluster.shared::cluster.b64 _, [%0];"
                             :: "r"(peerbar) : "memory");
            }
        } else {
            // x(s+1) into next buffer
            uint4 pk;
            pk.x = bfpack(xv.x, xv.y);  pk.y = bfpack(bfres(xv.x), bfres(xv.y));
            pk.z = bfpack(xv.z, xv.w);  pk.w = bfpack(bfres(xv.z), bfres(xv.w));
            *(uint4*)&C[(s + 1) & 1][xe] = pk;
        }
        gb += gstep;

        __syncthreads();   // local B writes visible

        // wait for peer's 64 h-entry arrivals (phase parity s&1)
        {
            const u32 par = (u32)(s & 1);
            asm volatile(
                "{\n\t.reg .pred P1;\n\t"
                "W_%=:\n\t"
                "mbarrier.try_wait.parity.acquire.cluster.shared::cta.b64 P1, [%0], %1, 0x989680;\n\t"
                "@!P1 bra W_%=;\n\t}"
                :: "r"(mybar), "r"(par) : "memory");
        }
    }

    asm volatile("barrier.cluster.arrive.aligned;" ::: "memory");
    asm volatile("barrier.cluster.wait.aligned;" ::: "memory");
}

// ===== fc head: out[b][t] = fcb + <h_fw,fcW[0:128]> + <h_bw,fcW[128:256]>
__global__ __launch_bounds__(256)
void birnn_fc(const float* __restrict__ fcW, const float* __restrict__ fcb,
              float* __restrict__ out)
{
    const int gw   = (blockIdx.x * blockDim.x + threadIdx.x) >> 5;
    const int lane = threadIdx.x & 31;
    const int b = gw >> 10;
    const int t = gw & 1023;

    const float4* hf = (const float4*)(g_h + ((size_t)b * SLEN + t) * HID);
    const float4* hb = (const float4*)(g_h + ((size_t)(BATCH + b) * SLEN + t) * HID);
    float4 a  = hf[lane];
    float4 c  = hb[lane];
    float4 wa = ((const float4*)fcW)[lane];
    float4 wb = ((const float4*)fcW)[32 + lane];

    float s = a.x*wa.x + a.y*wa.y + a.z*wa.z + a.w*wa.w
            + c.x*wb.x + c.y*wb.y + c.z*wb.z + c.w*wb.w;
    #pragma unroll
    for (int m = 16; m > 0; m >>= 1)
        s += __shfl_xor_sync(0xffffffffu, s, m);
    if (lane == 0) out[gw] = s + fcb[0];
}

extern "C" void kernel_launch(void* const* d_in, const int* in_sizes, int n_in,
                              void* d_out, int out_size)
{
    (void)in_sizes; (void)n_in; (void)out_size;
    const float* inputs = (const float*)d_in[0];
    const float* Wih_fw = (const float*)d_in[1];
    const float* Whh_fw = (const float*)d_in[2];
    const float* bih_fw = (const float*)d_in[3];
    const float* bhh_fw = (const float*)d_in[4];
    const float* Wih_bw = (const float*)d_in[5];
    const float* Whh_bw = (const float*)d_in[6];
    const float* bih_bw = (const float*)d_in[7];
    const float* bhh_bw = (const float*)d_in[8];
    const float* fcW    = (const float*)d_in[9];
    const float* fcb    = (const float*)d_in[10];
    float* out = (float*)d_out;

    birnn_recur<<<128, 256>>>(inputs, Whh_fw, Whh_bw, Wih_fw, Wih_bw,
                              bih_fw, bhh_fw, bih_bw, bhh_bw);
    birnn_fc<<<(BATCH * SLEN) / 8, 256>>>(fcW, fcb, out);
}

// round 10
// speedup vs baseline: 1.5293x; 1.5293x over previous
#include <cuda_runtime.h>
#include <cuda_fp16.h>
#include <cstdint>

#define SLEN 1024
#define BATCH 256
#define DIN 64
#define HID 128
#define KWROW 100          // words per B row: 96 real (192 fp16) + 4 pad

// h outputs for fc pass: [dir][b][t][j]
__device__ float g_h[2u * BATCH * SLEN * HID];

typedef unsigned int u32;

// pack two f32 -> f16x2 (lo16 = a0, hi16 = a1)
static __device__ __forceinline__ u32 hpack(float a0, float a1) {
    u32 r; asm("cvt.rn.f16x2.f32 %0, %1, %2;" : "=r"(r) : "f"(a1), "f"(a0)); return r;
}
static __device__ __forceinline__ float hres(float a) {
    return a - __half2float(__float2half_rn(a));
}
static __device__ __forceinline__ void mma16816h(float c[4], const u32 a[4], const u32 b[2]) {
    asm("mma.sync.aligned.m16n8k16.row.col.f32.f16.f16.f32 "
        "{%0,%1,%2,%3}, {%4,%5,%6,%7}, {%8,%9}, {%0,%1,%2,%3};"
        : "+f"(c[0]), "+f"(c[1]), "+f"(c[2]), "+f"(c[3])
        : "r"(a[0]), "r"(a[1]), "r"(a[2]), "r"(a[3]), "r"(b[0]), "r"(b[1]));
}
static __device__ __forceinline__ float fast_tanh(float x) {
    float e, r;
    asm("ex2.approx.f32 %0, %1;" : "=f"(e) : "f"(x * 2.8853900817779268f));
    asm("rcp.approx.f32 %0, %1;" : "=f"(r) : "f"(e + 1.0f));
    return fmaf(-2.0f, r, 1.0f);
}

// ===== Recurrence: 64 blocks (2 dir x 32 batch-groups of 8), 256 threads (8 warps).
// Per step: D[j(128), b(8)] = [Whh|Wih] . [h|x], K=192.
// fp16 2-product emulation: A = W hi/lo (static, registers), B = [h|x] single fp16.
// B tile double-buffered in smem; one __syncthreads per step.
__global__ __launch_bounds__(256, 1)
void birnn_recur(const float* __restrict__ inputs,
                 const float* __restrict__ Whh_fw, const float* __restrict__ Whh_bw,
                 const float* __restrict__ Wih_fw, const float* __restrict__ Wih_bw,
                 const float* __restrict__ bih_fw, const float* __restrict__ bhh_fw,
                 const float* __restrict__ bih_bw, const float* __restrict__ bhh_bw)
{
    __shared__ u32 C[2][8 * KWROW];     // [buf][batch 8][k-word 96 + 4 pad]

    const int tid  = threadIdx.x;
    const int lane = tid & 31;
    const int w    = tid >> 5;
    const int g  = lane >> 2;      // 0..7
    const int t4 = lane & 3;       // 0..3
    const int j0 = 16 * w;
    const int dir = blockIdx.x >> 5;
    const int bb  = (blockIdx.x & 31) * 8;

    const float* Whh = dir ? Whh_bw : Whh_fw;
    const float* Wih = dir ? Wih_bw : Wih_fw;

    // ---- static A fragments: rows j0+g, j0+g+8 over K=192, fp16 hi + lo ----
    u32 ah[12][4], al[12][4];
    #pragma unroll
    for (int kc = 0; kc < 12; ++kc) {
        const int kb = 16 * kc + 2 * t4;
        const float* r0 = (kc < 8) ? (Whh + (j0 + g) * HID + kb)
                                   : (Wih + (j0 + g) * DIN + (kb - HID));
        const float* r1 = (kc < 8) ? (Whh + (j0 + g + 8) * HID + kb)
                                   : (Wih + (j0 + g + 8) * DIN + (kb - HID));
        float2 v0 = *(const float2*)r0;
        float2 v1 = *(const float2*)r1;
        float2 v2 = *(const float2*)(r0 + 8);
        float2 v3 = *(const float2*)(r1 + 8);
        ah[kc][0] = hpack(v0.x, v0.y);  al[kc][0] = hpack(hres(v0.x), hres(v0.y));
        ah[kc][1] = hpack(v1.x, v1.y);  al[kc][1] = hpack(hres(v1.x), hres(v1.y));
        ah[kc][2] = hpack(v2.x, v2.y);  al[kc][2] = hpack(hres(v2.x), hres(v2.y));
        ah[kc][3] = hpack(v3.x, v3.y);  al[kc][3] = hpack(hres(v3.x), hres(v3.y));
    }

    float bias2[2];
    #pragma unroll
    for (int hh = 0; hh < 2; ++hh) {
        const int j = j0 + g + 8 * hh;
        bias2[hh] = dir ? (bih_bw[j] + bhh_bw[j]) : (bih_fw[j] + bhh_fw[j]);
    }

    // ---- zero both buffers (h0 = 0, pads 0) ----
    for (int i = tid; i < 2 * 8 * KWROW; i += 256)
        (&C[0][0])[i] = 0u;

    // ---- x loader: warp w <-> batch row w; lane covers k-dims 2*lane, 2*lane+1 ----
    const int t0 = dir ? (SLEN - 1) : 0;
    const int dt = dir ? -1 : 1;
    const int xb = w;
    const float* xptr = inputs + ((size_t)(bb + xb) * SLEN + t0) * DIN + lane * 2;
    const int xw = xb * KWROW + 64 + lane;    // word index of this thread's x pair

    __syncthreads();
    {
        float2 v = *(const float2*)xptr;
        C[0][xw] = hpack(v.x, v.y);
    }

    // ---- gmem h stream ----
    float* gbase = g_h + ((size_t)(dir * BATCH + bb) * SLEN + t0) * HID;
    const long gstep = (long)dt * HID;
    int goff[4];
    #pragma unroll
    for (int e = 0; e < 4; ++e)
        goff[e] = (2 * t4 + (e & 1)) * (SLEN * HID) + j0 + g + 8 * (e >> 1);

    __syncthreads();

    for (int s = 0; s < SLEN; ++s) {
        const u32* Rd = C[s & 1];

        // prefetch next x (hidden under MMA)
        float2 xn = make_float2(0.f, 0.f);
        if (s + 1 < SLEN) {
            xptr += dt * DIN;
            xn = *(const float2*)xptr;
        }

        // ---- 24 HMMA over K=192, 2 independent accumulator chains ----
        float a0[4] = {0.f, 0.f, 0.f, 0.f};
        float a1[4] = {0.f, 0.f, 0.f, 0.f};
        #pragma unroll
        for (int kc = 0; kc < 12; ++kc) {
            const int w0 = g * KWROW + kc * 8 + t4;
            u32 b[2];
            b[0] = Rd[w0];
            b[1] = Rd[w0 + 4];
            mma16816h(a0, ah[kc], b);
            mma16816h(a1, al[kc], b);
        }

        // ---- activate ----
        float v[4];
        #pragma unroll
        for (int e = 0; e < 4; ++e)
            v[e] = fast_tanh(a0[e] + a1[e] + bias2[e >> 1]);

        // ---- write h_{s+1} fp16 into the OTHER buffer + stream fp32 to gmem ----
        unsigned short* Wu = (unsigned short*)C[(s + 1) & 1];
        #pragma unroll
        for (int e = 0; e < 4; ++e) {
            const int b_ = 2 * t4 + (e & 1);
            const int j_ = j0 + g + 8 * (e >> 1);
            Wu[b_ * (2 * KWROW) + j_] = __half_as_ushort(__float2half_rn(v[e]));
            gbase[goff[e]] = v[e];
        }
        // x(t+1) into the other buffer
        C[(s + 1) & 1][xw] = hpack(xn.x, xn.y);
        gbase += gstep;

        __syncthreads();   // step-s reads done; buffer (s+1)&1 fully written
    }
}

// ===== fc head: out[b][t] = fcb + <h_fw,fcW[0:128]> + <h_bw,fcW[128:256]>
__global__ __launch_bounds__(256)
void birnn_fc(const float* __restrict__ fcW, const float* __restrict__ fcb,
              float* __restrict__ out)
{
    const int gw   = (blockIdx.x * blockDim.x + threadIdx.x) >> 5;
    const int lane = threadIdx.x & 31;
    const int b = gw >> 10;
    const int t = gw & 1023;

    const float4* hf = (const float4*)(g_h + ((size_t)b * SLEN + t) * HID);
    const float4* hb = (const float4*)(g_h + ((size_t)(BATCH + b) * SLEN + t) * HID);
    float4 a  = hf[lane];
    float4 c  = hb[lane];
    float4 wa = ((const float4*)fcW)[lane];
    float4 wb = ((const float4*)fcW)[32 + lane];

    float s = a.x*wa.x + a.y*wa.y + a.z*wa.z + a.w*wa.w
            + c.x*wb.x + c.y*wb.y + c.z*wb.z + c.w*wb.w;
    #pragma unroll
    for (int m = 16; m > 0; m >>= 1)
        s += __shfl_xor_sync(0xffffffffu, s, m);
    if (lane == 0) out[gw] = s + fcb[0];
}

extern "C" void kernel_launch(void* const* d_in, const int* in_sizes, int n_in,
                              void* d_out, int out_size)
{
    (void)in_sizes; (void)n_in; (void)out_size;
    const float* inputs = (const float*)d_in[0];
    const float* Wih_fw = (const float*)d_in[1];
    const float* Whh_fw = (const float*)d_in[2];
    const float* bih_fw = (const float*)d_in[3];
    const float* bhh_fw = (const float*)d_in[4];
    const float* Wih_bw = (const float*)d_in[5];
    const float* Whh_bw = (const float*)d_in[6];
    const float* bih_bw = (const float*)d_in[7];
    const float* bhh_bw = (const float*)d_in[8];
    const float* fcW    = (const float*)d_in[9];
    const float* fcb    = (const float*)d_in[10];
    float* out = (float*)d_out;

    birnn_recur<<<64, 256>>>(inputs, Whh_fw, Whh_bw, Wih_fw, Wih_bw,
                             bih_fw, bhh_fw, bih_bw, bhh_bw);
    birnn_fc<<<(BATCH * SLEN) / 8, 256>>>(fcW, fcb, out);
}

// round 11
// speedup vs baseline: 1.5815x; 1.0341x over previous
#include <cuda_runtime.h>
#include <cuda_fp16.h>
#include <cstdint>

#define SLEN 1024
#define BATCH 256
#define DIN 64
#define HID 128
#define KWROW 100          // words per B row: 96 real (192 fp16) + 4 pad

// h outputs for fc pass: [dir][b][t][j]
__device__ float g_h[2u * BATCH * SLEN * HID];

typedef unsigned int u32;

// pack two f32 -> f16x2 (lo16 = a0, hi16 = a1)
static __device__ __forceinline__ u32 hpack(float a0, float a1) {
    u32 r; asm("cvt.rn.f16x2.f32 %0, %1, %2;" : "=r"(r) : "f"(a1), "f"(a0)); return r;
}
static __device__ __forceinline__ float hres(float a) {
    return a - __half2float(__float2half_rn(a));
}
static __device__ __forceinline__ void mma16816h(float c[4], const u32 a[4], const u32 b[2]) {
    asm("mma.sync.aligned.m16n8k16.row.col.f32.f16.f16.f32 "
        "{%0,%1,%2,%3}, {%4,%5,%6,%7}, {%8,%9}, {%0,%1,%2,%3};"
        : "+f"(c[0]), "+f"(c[1]), "+f"(c[2]), "+f"(c[3])
        : "r"(a[0]), "r"(a[1]), "r"(a[2]), "r"(a[3]), "r"(b[0]), "r"(b[1]));
}
static __device__ __forceinline__ float tanh_mufu(float x) {
    float r; asm("tanh.approx.f32 %0, %1;" : "=f"(r) : "f"(x)); return r;
}

// ===== Recurrence: 64 blocks (2 dir x 32 batch-groups of 8), 256 threads (8 warps).
// Per step: D[j(128), b(8)] = [Whh|Wih] . [h|x], K=192.
// fp16 emulation: A = W hi/lo registers (lo only for the recurrent Whh chunks),
// B = [h|x] single fp16 plane, double-buffered, word-permuted for LDS.64 frags.
__global__ __launch_bounds__(256, 1)
void birnn_recur(const float* __restrict__ inputs,
                 const float* __restrict__ Whh_fw, const float* __restrict__ Whh_bw,
                 const float* __restrict__ Wih_fw, const float* __restrict__ Wih_bw,
                 const float* __restrict__ bih_fw, const float* __restrict__ bhh_fw,
                 const float* __restrict__ bih_bw, const float* __restrict__ bhh_bw)
{
    __shared__ u32 C[2][8 * KWROW];     // [buf][batch 8][k-word 96 + 4 pad]

    const int tid  = threadIdx.x;
    const int lane = tid & 31;
    const int w    = tid >> 5;
    const int g  = lane >> 2;      // 0..7
    const int t4 = lane & 3;       // 0..3
    const int j0 = 16 * w;
    const int dir = blockIdx.x >> 5;
    const int bb  = (blockIdx.x & 31) * 8;

    const float* Whh = dir ? Whh_bw : Whh_fw;
    const float* Wih = dir ? Wih_bw : Wih_fw;

    // ---- static A fragments: rows j0+g, j0+g+8 over K=192 ----
    // hi for all 12 kc; lo only for the 8 recurrent (Whh) kc.
    u32 ah[12][4], al[8][4];
    #pragma unroll
    for (int kc = 0; kc < 12; ++kc) {
        const int kb = 16 * kc + 2 * t4;
        const float* r0 = (kc < 8) ? (Whh + (j0 + g) * HID + kb)
                                   : (Wih + (j0 + g) * DIN + (kb - HID));
        const float* r1 = (kc < 8) ? (Whh + (j0 + g + 8) * HID + kb)
                                   : (Wih + (j0 + g + 8) * DIN + (kb - HID));
        float2 v0 = *(const float2*)r0;
        float2 v1 = *(const float2*)r1;
        float2 v2 = *(const float2*)(r0 + 8);
        float2 v3 = *(const float2*)(r1 + 8);
        ah[kc][0] = hpack(v0.x, v0.y);
        ah[kc][1] = hpack(v1.x, v1.y);
        ah[kc][2] = hpack(v2.x, v2.y);
        ah[kc][3] = hpack(v3.x, v3.y);
        if (kc < 8) {
            al[kc][0] = hpack(hres(v0.x), hres(v0.y));
            al[kc][1] = hpack(hres(v1.x), hres(v1.y));
            al[kc][2] = hpack(hres(v2.x), hres(v2.y));
            al[kc][3] = hpack(hres(v3.x), hres(v3.y));
        }
    }

    float bias2[2];
    #pragma unroll
    for (int hh = 0; hh < 2; ++hh) {
        const int j = j0 + g + 8 * hh;
        bias2[hh] = dir ? (bih_bw[j] + bhh_bw[j]) : (bih_fw[j] + bhh_fw[j]);
    }

    // ---- zero both buffers (h0 = 0, pads 0) ----
    for (int i = tid; i < 2 * 8 * KWROW; i += 256)
        (&C[0][0])[i] = 0u;

    // ---- x loader: warp w <-> batch row w; lane covers k-dims 2*lane, 2*lane+1.
    // Word-permuted position within the kc group: q -> ((q&3)<<1)|(q>>2).
    const int t0 = dir ? (SLEN - 1) : 0;
    const int dt = dir ? -1 : 1;
    const int xb = w;
    const float* xptr = inputs + ((size_t)(bb + xb) * SLEN + t0) * DIN + lane * 2;
    const int xq = lane & 7;
    const int xp = ((xq & 3) << 1) | (xq >> 2);
    const int xw = xb * KWROW + (8 + (lane >> 3)) * 8 + xp;

    __syncthreads();
    {
        float2 v = *(const float2*)xptr;
        C[0][xw] = hpack(v.x, v.y);
    }

    // ---- gmem h stream ----
    float* gbase = g_h + ((size_t)(dir * BATCH + bb) * SLEN + t0) * HID;
    const long gstep = (long)dt * HID;
    int goff[4];
    #pragma unroll
    for (int e = 0; e < 4; ++e)
        goff[e] = (2 * t4 + (e & 1)) * (SLEN * HID) + j0 + g + 8 * (e >> 1);

    // h smem write indices (permuted halves positions)
    int hoff[4];
    #pragma unroll
    for (int e = 0; e < 4; ++e) {
        const int b_ = 2 * t4 + (e & 1);
        const int j_ = j0 + g + 8 * (e >> 1);
        const int kc = j_ >> 4;
        const int q  = (j_ >> 1) & 7;
        const int p  = ((q & 3) << 1) | (q >> 2);
        hoff[e] = (b_ * KWROW + kc * 8 + p) * 2 + (j_ & 1);
    }

    __syncthreads();

    for (int s = 0; s < SLEN; ++s) {
        const u32* Rd = C[s & 1];

        // prefetch next x (hidden under MMA)
        float2 xn = make_float2(0.f, 0.f);
        if (s + 1 < SLEN) {
            xptr += dt * DIN;
            xn = *(const float2*)xptr;
        }

        // ---- 20 HMMA over K=192 (hi all kc, lo on recurrent kc only) ----
        float a0[4] = {0.f, 0.f, 0.f, 0.f};
        float a1[4] = {0.f, 0.f, 0.f, 0.f};
        #pragma unroll
        for (int kc = 0; kc < 12; ++kc) {
            uint2 bw = *(const uint2*)(Rd + g * KWROW + kc * 8 + 2 * t4);
            u32 b[2] = { bw.x, bw.y };
            mma16816h(a0, ah[kc], b);
            if (kc < 8) mma16816h(a1, al[kc], b);
        }

        // ---- activate (MUFU.TANH) ----
        float v[4];
        #pragma unroll
        for (int e = 0; e < 4; ++e)
            v[e] = tanh_mufu(a0[e] + a1[e] + bias2[e >> 1]);

        // ---- write h_{s+1} fp16 into the OTHER buffer + stream fp32 to gmem ----
        unsigned short* Wu = (unsigned short*)C[(s + 1) & 1];
        #pragma unroll
        for (int e = 0; e < 4; ++e) {
            Wu[hoff[e]] = __half_as_ushort(__float2half_rn(v[e]));
            gbase[goff[e]] = v[e];
        }
        // x(t+1) into the other buffer
        C[(s + 1) & 1][xw] = hpack(xn.x, xn.y);
        gbase += gstep;

        __syncthreads();   // step-s reads done; buffer (s+1)&1 fully written
    }
}

// ===== fc head: out[b][t] = fcb + <h_fw,fcW[0:128]> + <h_bw,fcW[128:256]>
__global__ __launch_bounds__(256)
void birnn_fc(const float* __restrict__ fcW, const float* __restrict__ fcb,
              float* __restrict__ out)
{
    const int gw   = (blockIdx.x * blockDim.x + threadIdx.x) >> 5;
    const int lane = threadIdx.x & 31;
    const int b = gw >> 10;
    const int t = gw & 1023;

    const float4* hf = (const float4*)(g_h + ((size_t)b * SLEN + t) * HID);
    const float4* hb = (const float4*)(g_h + ((size_t)(BATCH + b) * SLEN + t) * HID);
    float4 a  = hf[lane];
    float4 c  = hb[lane];
    float4 wa = ((const float4*)fcW)[lane];
    float4 wb = ((const float4*)fcW)[32 + lane];

    float s = a.x*wa.x + a.y*wa.y + a.z*wa.z + a.w*wa.w
            + c.x*wb.x + c.y*wb.y + c.z*wb.z + c.w*wb.w;
    #pragma unroll
    for (int m = 16; m > 0; m >>= 1)
        s += __shfl_xor_sync(0xffffffffu, s, m);
    if (lane == 0) out[gw] = s + fcb[0];
}

extern "C" void kernel_launch(void* const* d_in, const int* in_sizes, int n_in,
                              void* d_out, int out_size)
{
    (void)in_sizes; (void)n_in; (void)out_size;
    const float* inputs = (const float*)d_in[0];
    const float* Wih_fw = (const float*)d_in[1];
    const float* Whh_fw = (const float*)d_in[2];
    const float* bih_fw = (const float*)d_in[3];
    const float* bhh_fw = (const float*)d_in[4];
    const float* Wih_bw = (const float*)d_in[5];
    const float* Whh_bw = (const float*)d_in[6];
    const float* bih_bw = (const float*)d_in[7];
    const float* bhh_bw = (const float*)d_in[8];
    const float* fcW    = (const float*)d_in[9];
    const float* fcb    = (const float*)d_in[10];
    float* out = (float*)d_out;

    birnn_recur<<<64, 256>>>(inputs, Whh_fw, Whh_bw, Wih_fw, Wih_bw,
                             bih_fw, bhh_fw, bih_bw, bhh_bw);
    birnn_fc<<<(BATCH * SLEN) / 8, 256>>>(fcW, fcb, out);
}